// round 3
// baseline (speedup 1.0000x reference)
#include <cuda_runtime.h>
#include <cuda_bf16.h>

// ---------------------------------------------------------------------------
// VisionExperts: 3-expert vision MoE
//   E0: s=448 p=14 g=32 c=1024  (no input resize, no feat resize)
//   E1: s=336 p=14 g=24 c=768   (input 448->336, feat 24->32)
//   E2: s=448 p=32 g=14 c=1152  (feat 14->32)
// out[64,1024,1024] = sum_i w_i[b] * (proj_i(resize(tower_i(patches_i(x)))))
// ---------------------------------------------------------------------------

#define BM 128
#define BN 128
#define BK 8
#define TM 8
#define TN 8

// Scratch (device globals; no runtime allocation allowed)
__device__ float g_x336[64 * 3 * 336 * 336];        //  86.7 MB
__device__ float g_patches[38535168];               // 154   MB (max of E0/E2)
__device__ float g_feat[67108864];                  // 268   MB (max tower out)
__device__ float g_featr[75497472];                 // 302   MB (65536 x 1152)
__device__ float g_w[3 * 64];                       // routing weight per (expert, sample)

// ---------------------------------------------------------------------------
__global__ void compute_weights_kernel(const int* __restrict__ sel,
                                       const float* __restrict__ rw) {
    int i = threadIdx.x;
    if (i < 192) {
        int e = i / 64, b = i % 64;
        float w = 0.0f;
        if (sel[2 * b + 0] == e) w += rw[2 * b + 0];
        if (sel[2 * b + 1] == e) w += rw[2 * b + 1];
        g_w[i] = w;
    }
}

// Bilinear align_corners 448 -> 336 (expert 1 only)
__global__ void resize_input_kernel(const float* __restrict__ x,
                                    float* __restrict__ y) {
    long long idx = (long long)blockIdx.x * blockDim.x + threadIdx.x;
    const long long total = 64LL * 3 * 336 * 336;
    if (idx >= total) return;
    int ox = (int)(idx % 336);
    int oy = (int)((idx / 336) % 336);
    int bc = (int)(idx / (336 * 336));
    int b = bc / 3;
    if (g_w[1 * 64 + b] == 0.0f) return;   // expert 1 not routed for this sample

    const float scale = 447.0f / 335.0f;
    float fy = oy * scale;
    float fx = ox * scale;
    int y0 = (int)floorf(fy); int y1 = min(y0 + 1, 447);
    int x0 = (int)floorf(fx); int x1 = min(x0 + 1, 447);
    float ty = fy - (float)y0, tx = fx - (float)x0;
    const float* p = x + (size_t)bc * 448 * 448;
    float v00 = p[y0 * 448 + x0], v01 = p[y0 * 448 + x1];
    float v10 = p[y1 * 448 + x0], v11 = p[y1 * 448 + x1];
    float r0 = v00 + (v01 - v00) * tx;
    float r1 = v10 + (v11 - v10) * tx;
    y[idx] = r0 + (r1 - r0) * ty;
}

// patches[b, gy*g+gx, ch*p*p + py*p + px] = src[b, ch, gy*p+py, gx*p+px]
__global__ void im2col_kernel(const float* __restrict__ src,
                              float* __restrict__ dst,
                              int g, int p, int s, int expert) {
    long long idx = (long long)blockIdx.x * blockDim.x + threadIdx.x;
    long long total = 64LL * g * g * 3 * p * p;
    if (idx >= total) return;
    int K = 3 * p * p;
    int k = (int)(idx % K);
    long long t = idx / K;
    int token = (int)(t % (g * g));
    int b = (int)(t / (g * g));
    if (g_w[expert * 64 + b] == 0.0f) return;
    int ch = k / (p * p);
    int r = k % (p * p);
    int py = r / p, px = r % p;
    int gy = token / g, gx = token % g;
    dst[idx] = src[(((size_t)b * 3 + ch) * s + (gy * p + py)) * s + (gx * p + px)];
}

// Feature grid resize g x g -> 32 x 32 (channels-last, per sample)
__global__ void feat_resize_kernel(const float* __restrict__ in,
                                   float* __restrict__ out,
                                   int g, int c, int expert) {
    int token = blockIdx.x & 1023;
    int b = blockIdx.x >> 10;
    if (g_w[expert * 64 + b] == 0.0f) return;
    int oy = token >> 5, ox = token & 31;
    float scale = (float)(g - 1) / 31.0f;
    float fy = oy * scale, fx = ox * scale;
    int y0 = (int)floorf(fy), x0 = (int)floorf(fx);
    int y1 = min(y0 + 1, g - 1), x1 = min(x0 + 1, g - 1);
    float ty = fy - (float)y0, tx = fx - (float)x0;
    float w00 = (1.0f - ty) * (1.0f - tx), w01 = (1.0f - ty) * tx;
    float w10 = ty * (1.0f - tx),          w11 = ty * tx;
    const float* base = in + (size_t)b * g * g * c;
    const float* p00 = base + (size_t)(y0 * g + x0) * c;
    const float* p01 = base + (size_t)(y0 * g + x1) * c;
    const float* p10 = base + (size_t)(y1 * g + x0) * c;
    const float* p11 = base + (size_t)(y1 * g + x1) * c;
    float* o = out + ((size_t)b * 1024 + token) * c;
    for (int i = threadIdx.x; i < c; i += blockDim.x)
        o[i] = w00 * p00[i] + w01 * p01[i] + w10 * p10[i] + w11 * p11[i];
}

// ---------------------------------------------------------------------------
// 128x128x8 fp32 SGEMM, 256 threads, 8x8 per thread.
// MODE 0: C = A@B + bias              (tower; skip blocks of unrouted samples)
// MODE 1: C += w[b] * (A@B + bias)    (projector accumulate; tps == 1024)
// ---------------------------------------------------------------------------
template <int MODE>
__global__ __launch_bounds__(256, 2) void sgemm_kernel(
    int M, int N, int K, int tps, int expert,
    const float* __restrict__ A, const float* __restrict__ B,
    const float* __restrict__ bias, float* __restrict__ C) {
    const int bx = blockIdx.x, by = blockIdx.y;
    const int rowStart = by * BM;

    // routing skip: all samples covered by this M-block unrouted -> no work
    {
        int bLo = rowStart / tps;
        int bHi = (rowStart + BM - 1) / tps;
        bool any = false;
        for (int b = bLo; b <= bHi; ++b)
            any = any || (g_w[expert * 64 + b] != 0.0f);
        if (!any) return;
    }

    __shared__ float As[BK][BM];   // transposed A tile
    __shared__ float Bs[BK][BN];

    const int tid = threadIdx.x;
    const int trow = tid / 16;          // 0..15
    const int tcol = tid % 16;          // 0..15

    const int aRow = tid >> 1;          // 0..127
    const int aCol = (tid & 1) * 4;     // 0 or 4
    const int bRow = tid >> 5;          // 0..7
    const int bCol = (tid & 31) * 4;    // 0..124

    const float* Aptr = A + (size_t)(rowStart + aRow) * K + aCol;
    const float* Bptr = B + (size_t)bRow * N + (size_t)bx * BN + bCol;

    float acc[TM][TN];
#pragma unroll
    for (int i = 0; i < TM; ++i)
#pragma unroll
        for (int j = 0; j < TN; ++j) acc[i][j] = 0.0f;

    for (int k0 = 0; k0 < K; k0 += BK) {
        float4 av = make_float4(0.f, 0.f, 0.f, 0.f);
        if (k0 + aCol < K)  // K % 4 == 0 guarantees whole-vector validity
            av = *(const float4*)(Aptr + k0);
        As[aCol + 0][aRow] = av.x;
        As[aCol + 1][aRow] = av.y;
        As[aCol + 2][aRow] = av.z;
        As[aCol + 3][aRow] = av.w;

        float4 bv = make_float4(0.f, 0.f, 0.f, 0.f);
        if (k0 + bRow < K)
            bv = *(const float4*)(Bptr + (size_t)k0 * N);
        *(float4*)&Bs[bRow][bCol] = bv;

        __syncthreads();
#pragma unroll
        for (int kk = 0; kk < BK; ++kk) {
            float aReg[TM], bReg[TN];
#pragma unroll
            for (int i = 0; i < TM; ++i) aReg[i] = As[kk][trow * TM + i];
#pragma unroll
            for (int j = 0; j < TN; ++j) bReg[j] = Bs[kk][tcol * TN + j];
#pragma unroll
            for (int i = 0; i < TM; ++i)
#pragma unroll
                for (int j = 0; j < TN; ++j)
                    acc[i][j] += aReg[i] * bReg[j];
        }
        __syncthreads();
    }

    const int colStart = bx * BN + tcol * TN;
    float bb[TN];
#pragma unroll
    for (int j = 0; j < TN; ++j) bb[j] = bias[colStart + j];

    if (MODE == 0) {
#pragma unroll
        for (int i = 0; i < TM; ++i) {
            int row = rowStart + trow * TM + i;
            float* Crow = C + (size_t)row * N + colStart;
#pragma unroll
            for (int j = 0; j < TN; ++j) Crow[j] = acc[i][j] + bb[j];
        }
    } else {
        // tps == 1024 and BM | 1024 -> whole block belongs to one sample
        float w = g_w[expert * 64 + rowStart / tps];
#pragma unroll
        for (int i = 0; i < TM; ++i) {
            int row = rowStart + trow * TM + i;
            float* Crow = C + (size_t)row * N + colStart;
#pragma unroll
            for (int j = 0; j < TN; ++j) Crow[j] += w * (acc[i][j] + bb[j]);
        }
    }
}

// ---------------------------------------------------------------------------
extern "C" void kernel_launch(void* const* d_in, const int* in_sizes, int n_in,
                              void* d_out, int out_size) {
    const float* x   = (const float*)d_in[0];
    const int*   sel = (const int*)d_in[1];
    const float* rw  = (const float*)d_in[2];
    const float* wt0 = (const float*)d_in[3];
    const float* bt0 = (const float*)d_in[4];
    const float* wp0 = (const float*)d_in[5];
    const float* bp0 = (const float*)d_in[6];
    const float* wt1 = (const float*)d_in[7];
    const float* bt1 = (const float*)d_in[8];
    const float* wp1 = (const float*)d_in[9];
    const float* bp1 = (const float*)d_in[10];
    const float* wt2 = (const float*)d_in[11];
    const float* bt2 = (const float*)d_in[12];
    const float* wp2 = (const float*)d_in[13];
    const float* bp2 = (const float*)d_in[14];
    float* out = (float*)d_out;

    float* px336;  cudaGetSymbolAddress((void**)&px336,  g_x336);
    float* ppatch; cudaGetSymbolAddress((void**)&ppatch, g_patches);
    float* pfeat;  cudaGetSymbolAddress((void**)&pfeat,  g_feat);
    float* pfeatr; cudaGetSymbolAddress((void**)&pfeatr, g_featr);

    compute_weights_kernel<<<1, 192>>>(sel, rw);
    cudaMemsetAsync(d_out, 0, (size_t)out_size * sizeof(float), 0);

    // ---------------- Expert 0: s=448 p=14 g=32 c=1024 ----------------
    {
        const int g = 32, p = 14, c = 1024;
        const int M = 64 * g * g;          // 65536
        const int K = 3 * p * p;           // 588
        long long tot = (long long)M * K;
        im2col_kernel<<<(unsigned)((tot + 255) / 256), 256>>>(x, ppatch, g, p, 448, 0);
        sgemm_kernel<0><<<dim3(c / BN, M / BM), 256>>>(M, c, K, g * g, 0,
                                                       ppatch, wt0, bt0, pfeat);
        // g == 32: no feature resize; projector reads pfeat
        sgemm_kernel<1><<<dim3(1024 / BN, 65536 / BM), 256>>>(65536, 1024, c, 1024, 0,
                                                              pfeat, wp0, bp0, out);
    }

    // ---------------- Expert 1: s=336 p=14 g=24 c=768 -----------------
    {
        const int g = 24, p = 14, c = 768;
        const int M = 64 * g * g;          // 36864
        const int K = 3 * p * p;           // 588
        long long rtot = 64LL * 3 * 336 * 336;
        resize_input_kernel<<<(unsigned)((rtot + 255) / 256), 256>>>(x, px336);
        long long tot = (long long)M * K;
        im2col_kernel<<<(unsigned)((tot + 255) / 256), 256>>>(px336, ppatch, g, p, 336, 1);
        sgemm_kernel<0><<<dim3(c / BN, M / BM), 256>>>(M, c, K, g * g, 1,
                                                       ppatch, wt1, bt1, pfeat);
        feat_resize_kernel<<<64 * 1024, 256>>>(pfeat, pfeatr, g, c, 1);
        sgemm_kernel<1><<<dim3(1024 / BN, 65536 / BM), 256>>>(65536, 1024, c, 1024, 1,
                                                              pfeatr, wp1, bp1, out);
    }

    // ---------------- Expert 2: s=448 p=32 g=14 c=1152 ----------------
    {
        const int g = 14, p = 32, c = 1152;
        const int M = 64 * g * g;          // 12544
        const int K = 3 * p * p;           // 3072
        long long tot = (long long)M * K;
        im2col_kernel<<<(unsigned)((tot + 255) / 256), 256>>>(x, ppatch, g, p, 448, 2);
        sgemm_kernel<0><<<dim3(c / BN, M / BM), 256>>>(M, c, K, g * g, 2,
                                                       ppatch, wt2, bt2, pfeat);
        feat_resize_kernel<<<64 * 1024, 256>>>(pfeat, pfeatr, g, c, 2);
        sgemm_kernel<1><<<dim3(1024 / BN, 65536 / BM), 256>>>(65536, 1024, c, 1024, 2,
                                                              pfeatr, wp2, bp2, out);
    }
}

// round 7
// speedup vs baseline: 2.1430x; 2.1430x over previous
#include <cuda_runtime.h>
#include <cuda_bf16.h>
#include <cstdint>

// ===========================================================================
// VisionExperts via base-ISA tensor cores (mma.sync bf16, 3-pass split):
//   C = (Ah+Al)(Bh+Bl)^T ~= AhBh + AhBl + AlBh   (fp32 accumulate)
// cp.async 16B -> SW128 smem tiles -> ldmatrix -> HMMA.16816.
//   E0: s=448 p=14 g=32 c=1024   E1: s=336 p=14 g=24 c=768   E2: s=448 p=32 g=14 c=1152
// ===========================================================================

// ---------------- device scratch (globals; no runtime alloc) ----------------
__device__ float         g_x336[21676032];        //  86.7 MB
__device__ __nv_bfloat16 g_patch_h[41943040];     //  84 MB   [M, Kpad]
__device__ __nv_bfloat16 g_patch_l[41943040];     //  84 MB
__device__ __nv_bfloat16 g_featA_h[75497472];     // 151 MB   [65536, c]
__device__ __nv_bfloat16 g_featA_l[75497472];     // 151 MB
__device__ float         g_feat[28311552];        // 113 MB   tower fp32 out (E1/E2)
__device__ __nv_bfloat16 g_wT_h[3538944];         //   7 MB   [N, Kpad]
__device__ __nv_bfloat16 g_wT_l[3538944];
__device__ float         g_w[192];                // routing weight [expert][b]

// ---------------- helpers ----------------
__device__ __forceinline__ uint32_t smem_u32(const void* p) {
    uint32_t a;
    asm("{ .reg .u64 t; cvta.to.shared.u64 t, %1; cvt.u32.u64 %0, t; }" : "=r"(a) : "l"(p));
    return a;
}
#define CP_ASYNC16(saddr, gptr) \
    asm volatile("cp.async.cg.shared.global [%0], [%1], 16;" :: "r"(saddr), "l"(gptr))
#define CP_COMMIT() asm volatile("cp.async.commit_group;" ::: "memory")
#define LDSM4(d0, d1, d2, d3, addr) \
    asm volatile("ldmatrix.sync.aligned.m8n8.x4.shared.b16 {%0,%1,%2,%3}, [%4];" \
                 : "=r"(d0), "=r"(d1), "=r"(d2), "=r"(d3) : "r"(addr))
#define MMA16816(d, a, b) \
    asm volatile("mma.sync.aligned.m16n8k16.row.col.f32.bf16.bf16.f32 " \
                 "{%0,%1,%2,%3}, {%4,%5,%6,%7}, {%8,%9}, {%0,%1,%2,%3};" \
                 : "+f"((d)[0]), "+f"((d)[1]), "+f"((d)[2]), "+f"((d)[3]) \
                 : "r"((a)[0]), "r"((a)[1]), "r"((a)[2]), "r"((a)[3]), \
                   "r"((b)[0]), "r"((b)[1]))

#define SW128(o) ((o) ^ (((o) >> 3) & 0x70))

__device__ __forceinline__ void split2(float v, __nv_bfloat16& h, __nv_bfloat16& l) {
    h = __float2bfloat16(v);
    l = __float2bfloat16(v - __bfloat162float(h));
}

// ---------------- small kernels ----------------
__global__ void compute_weights_kernel(const int* __restrict__ sel,
                                       const float* __restrict__ rw) {
    int i = threadIdx.x;
    if (i < 192) {
        int e = i / 64, b = i % 64;
        float w = 0.0f;
        if (sel[2 * b + 0] == e) w += rw[2 * b + 0];
        if (sel[2 * b + 1] == e) w += rw[2 * b + 1];
        g_w[i] = w;
    }
}

__global__ void resize_input_kernel(const float* __restrict__ x, float* __restrict__ y) {
    long long idx = (long long)blockIdx.x * blockDim.x + threadIdx.x;
    const long long total = 64LL * 3 * 336 * 336;
    if (idx >= total) return;
    int ox = (int)(idx % 336);
    int oy = (int)((idx / 336) % 336);
    int bc = (int)(idx / (336 * 336));
    int b = bc / 3;
    if (g_w[64 + b] == 0.0f) return;
    const float scale = 447.0f / 335.0f;
    float fy = oy * scale, fx = ox * scale;
    int y0 = (int)floorf(fy); int y1 = min(y0 + 1, 447);
    int x0 = (int)floorf(fx); int x1 = min(x0 + 1, 447);
    float ty = fy - y0, tx = fx - x0;
    const float* p = x + (size_t)bc * 448 * 448;
    float v00 = p[y0 * 448 + x0], v01 = p[y0 * 448 + x1];
    float v10 = p[y1 * 448 + x0], v11 = p[y1 * 448 + x1];
    float r0 = v00 + (v01 - v00) * tx;
    float r1 = v10 + (v11 - v10) * tx;
    y[idx] = r0 + (r1 - r0) * ty;
}

// im2col + bf16 split, K padded to Kpad with zeros
__global__ void im2col_split_kernel(const float* __restrict__ src,
                                    __nv_bfloat16* __restrict__ dh,
                                    __nv_bfloat16* __restrict__ dl,
                                    int g, int p, int s, int Kpad, int expert) {
    long long idx = (long long)blockIdx.x * blockDim.x + threadIdx.x;
    long long total = 64LL * g * g * Kpad;
    if (idx >= total) return;
    int k = (int)(idx % Kpad);
    long long t = idx / Kpad;
    int token = (int)(t % (g * g));
    int b = (int)(t / (g * g));
    if (g_w[expert * 64 + b] == 0.0f) return;
    float v = 0.0f;
    int K = 3 * p * p;
    if (k < K) {
        int ch = k / (p * p);
        int r = k % (p * p);
        int py = r / p, px = r % p;
        int gy = token / g, gx = token % g;
        v = src[(((size_t)b * 3 + ch) * s + (gy * p + py)) * s + (gx * p + px)];
    }
    __nv_bfloat16 h, l; split2(v, h, l);
    dh[idx] = h; dl[idx] = l;
}

// w[K,N] -> wT[N,Kpad] (zero pad) + bf16 split, 32x32 smem tiles
__global__ void transpose_split_kernel(const float* __restrict__ w,
                                       __nv_bfloat16* __restrict__ th,
                                       __nv_bfloat16* __restrict__ tl,
                                       int K, int N, int Kpad) {
    __shared__ float t[32][33];
    int k0 = blockIdx.y * 32, n0 = blockIdx.x * 32;
    int kk = k0 + threadIdx.y, nn = n0 + threadIdx.x;
    t[threadIdx.y][threadIdx.x] = (kk < K && nn < N) ? w[(size_t)kk * N + nn] : 0.0f;
    __syncthreads();
    int on = n0 + threadIdx.y, ok = k0 + threadIdx.x;
    if (on < N && ok < Kpad) {
        __nv_bfloat16 h, l; split2(t[threadIdx.x][threadIdx.y], h, l);
        th[(size_t)on * Kpad + ok] = h;
        tl[(size_t)on * Kpad + ok] = l;
    }
}

// feature grid resize g x g -> 32 x 32 with bf16 split output
__global__ void feat_resize_split_kernel(const float* __restrict__ in,
                                         __nv_bfloat16* __restrict__ oh,
                                         __nv_bfloat16* __restrict__ ol,
                                         int g, int c, int expert) {
    int token = blockIdx.x & 1023;
    int b = blockIdx.x >> 10;
    if (g_w[expert * 64 + b] == 0.0f) return;
    int oy = token >> 5, ox = token & 31;
    float scale = (float)(g - 1) / 31.0f;
    float fy = oy * scale, fx = ox * scale;
    int y0 = (int)floorf(fy), x0 = (int)floorf(fx);
    int y1 = min(y0 + 1, g - 1), x1 = min(x0 + 1, g - 1);
    float ty = fy - y0, tx = fx - x0;
    float w00 = (1.f - ty) * (1.f - tx), w01 = (1.f - ty) * tx;
    float w10 = ty * (1.f - tx),         w11 = ty * tx;
    const float* base = in + (size_t)b * g * g * c;
    const float* p00 = base + (size_t)(y0 * g + x0) * c;
    const float* p01 = base + (size_t)(y0 * g + x1) * c;
    const float* p10 = base + (size_t)(y1 * g + x0) * c;
    const float* p11 = base + (size_t)(y1 * g + x1) * c;
    size_t row = (size_t)b * 1024 + token;
    for (int i = threadIdx.x; i < c; i += blockDim.x) {
        float v = w00 * p00[i] + w01 * p01[i] + w10 * p10[i] + w11 * p11[i];
        __nv_bfloat16 h, l; split2(v, h, l);
        oh[row * c + i] = h; ol[row * c + i] = l;
    }
}

// ===========================================================================
// mma.sync GEMM: D[128 x 128] = (Ah+Al)[128,K] @ (Bh+Bl)[128,K]^T (3 passes).
// SW128 smem stages of BK=64 (Ah|Al|Bh|Bl @ 16KB each), double-buffered.
// 256 threads, 8 warps, warp tile 64x32 (warp grid 2x4).
// MODE 0: tower -> split bf16 (Ch/Cl, ldc)    MODE 1: tower -> fp32 (C, ldc)
// MODE 2: proj  -> C[row*1024+col] += w_b * (v + bias)
// ===========================================================================
#define STAGE_BYTES 65536

__device__ __forceinline__ void load_stage(
    uint32_t sb, const __nv_bfloat16* Ah, const __nv_bfloat16* Al,
    const __nv_bfloat16* Bh, const __nv_bfloat16* Bl,
    int rowStart, int colStart, int Kpad, int k0, int tid) {
#pragma unroll 4
    for (int c = tid; c < 4096; c += 256) {
        int half = (c >> 10) & 1;
        int cc = c & 1023;
        int r = cc >> 3, kc = cc & 7;
        const __nv_bfloat16* gp;
        uint32_t so;
        if (c < 2048) {
            gp = (half ? Al : Ah) + (size_t)(rowStart + r) * Kpad + k0 + kc * 8;
            so = sb + half * 16384 + SW128(r * 128 + kc * 16);
        } else {
            gp = (half ? Bl : Bh) + (size_t)(colStart + r) * Kpad + k0 + kc * 8;
            so = sb + 32768 + half * 16384 + SW128(r * 128 + kc * 16);
        }
        CP_ASYNC16(so, (const void*)gp);
    }
}

template <int MODE>
__global__ __launch_bounds__(256, 1) void gemm_mma(
    int Kpad, int tps, int expert,
    const __nv_bfloat16* __restrict__ Ah, const __nv_bfloat16* __restrict__ Al,
    const __nv_bfloat16* __restrict__ Bh, const __nv_bfloat16* __restrict__ Bl,
    const float* __restrict__ bias,
    float* __restrict__ C, __nv_bfloat16* __restrict__ Ch, __nv_bfloat16* __restrict__ Cl,
    int ldc) {
    const int tid = threadIdx.x;
    const int wid = tid >> 5, lane = tid & 31;
    const int rowStart = blockIdx.y * 128;
    const int colStart = blockIdx.x * 128;

    // routing skip: all samples covered by this M-block unrouted -> no work
    {
        int bLo = rowStart / tps, bHi = (rowStart + 127) / tps;
        bool any = false;
        for (int b = bLo; b <= bHi; ++b) any = any || (g_w[expert * 64 + b] != 0.0f);
        if (!any) return;
    }

    extern __shared__ __align__(1024) char smem[];
    const uint32_t sb0 = smem_u32(smem);

    const int wm = (wid >> 2) * 64;      // warp m-offset within block
    const int wn = (wid & 3) * 32;       // warp n-offset within block

    float acc[4][4][4];
#pragma unroll
    for (int i = 0; i < 4; ++i)
#pragma unroll
        for (int j = 0; j < 4; ++j)
#pragma unroll
            for (int r = 0; r < 4; ++r) acc[i][j][r] = 0.0f;

    const int KBn = Kpad >> 6;

    // lane-dependent ldmatrix address components
    const int arow = wm + (lane & 15);
    const int alo  = lane >> 4;                         // 0/1: k-chunk half
    const int bmat = lane >> 3;
    const int brow = ((bmat >> 1) << 3) + (lane & 7);   // n-row within 16
    const int bko  = bmat & 1;                          // k-chunk half

    load_stage(sb0, Ah, Al, Bh, Bl, rowStart, colStart, Kpad, 0, tid);
    CP_COMMIT();

    for (int kb = 0; kb < KBn; ++kb) {
        if (kb + 1 < KBn) {
            load_stage(sb0 + ((kb + 1) & 1) * STAGE_BYTES, Ah, Al, Bh, Bl,
                       rowStart, colStart, Kpad, (kb + 1) << 6, tid);
            CP_COMMIT();
            asm volatile("cp.async.wait_group 1;" ::: "memory");
        } else {
            asm volatile("cp.async.wait_group 0;" ::: "memory");
        }
        __syncthreads();

        const uint32_t sb = sb0 + (kb & 1) * STAGE_BYTES;
#pragma unroll
        for (int kk = 0; kk < 4; ++kk) {
            uint32_t ah[4][4], al[4][4], bh[4][2], bl[4][2];
#pragma unroll
            for (int mi = 0; mi < 4; ++mi) {
                uint32_t off = SW128((arow + 16 * mi) * 128 + (kk * 2 + alo) * 16);
                LDSM4(ah[mi][0], ah[mi][1], ah[mi][2], ah[mi][3], sb + off);
                LDSM4(al[mi][0], al[mi][1], al[mi][2], al[mi][3], sb + 16384 + off);
            }
#pragma unroll
            for (int p = 0; p < 2; ++p) {
                uint32_t off = SW128((wn + p * 16 + brow) * 128 + (kk * 2 + bko) * 16);
                LDSM4(bh[2 * p][0], bh[2 * p][1], bh[2 * p + 1][0], bh[2 * p + 1][1],
                      sb + 32768 + off);
                LDSM4(bl[2 * p][0], bl[2 * p][1], bl[2 * p + 1][0], bl[2 * p + 1][1],
                      sb + 49152 + off);
            }
#pragma unroll
            for (int mi = 0; mi < 4; ++mi)
#pragma unroll
                for (int nj = 0; nj < 4; ++nj) {
                    MMA16816(acc[mi][nj], ah[mi], bh[nj]);
                    MMA16816(acc[mi][nj], ah[mi], bl[nj]);
                    MMA16816(acc[mi][nj], al[mi], bh[nj]);
                }
        }
        __syncthreads();
    }

    // -------- epilogue straight from registers --------
    const int tq = lane >> 2;            // row within 8
    const int tr2 = (lane & 3) * 2;      // col pair
    if (MODE == 2) {
        float w = g_w[expert * 64 + (rowStart >> 10)];
#pragma unroll
        for (int nj = 0; nj < 4; ++nj) {
            int col = colStart + wn + nj * 8 + tr2;
            float b0 = bias[col], b1 = bias[col + 1];
#pragma unroll
            for (int mi = 0; mi < 4; ++mi) {
                int row0 = rowStart + wm + mi * 16 + tq;
                float* p0 = C + (size_t)row0 * 1024 + col;
                float* p1 = p0 + 8 * 1024;
                p0[0] += w * (acc[mi][nj][0] + b0);
                p0[1] += w * (acc[mi][nj][1] + b1);
                p1[0] += w * (acc[mi][nj][2] + b0);
                p1[1] += w * (acc[mi][nj][3] + b1);
            }
        }
    } else if (MODE == 0) {
#pragma unroll
        for (int nj = 0; nj < 4; ++nj) {
            int col = colStart + wn + nj * 8 + tr2;
            float b0 = bias[col], b1 = bias[col + 1];
#pragma unroll
            for (int mi = 0; mi < 4; ++mi) {
                int row0 = rowStart + wm + mi * 16 + tq;
#pragma unroll
                for (int h = 0; h < 2; ++h) {
                    int row = row0 + h * 8;
                    float v0 = acc[mi][nj][2 * h + 0] + b0;
                    float v1 = acc[mi][nj][2 * h + 1] + b1;
                    __nv_bfloat16 h0, l0, h1, l1;
                    split2(v0, h0, l0); split2(v1, h1, l1);
                    __nv_bfloat162 ph; ph.x = h0; ph.y = h1;
                    __nv_bfloat162 pl; pl.x = l0; pl.y = l1;
                    *(__nv_bfloat162*)(Ch + (size_t)row * ldc + col) = ph;
                    *(__nv_bfloat162*)(Cl + (size_t)row * ldc + col) = pl;
                }
            }
        }
    } else {
#pragma unroll
        for (int nj = 0; nj < 4; ++nj) {
            int col = colStart + wn + nj * 8 + tr2;
            float b0 = bias[col], b1 = bias[col + 1];
#pragma unroll
            for (int mi = 0; mi < 4; ++mi) {
                int row0 = rowStart + wm + mi * 16 + tq;
                float* p0 = C + (size_t)row0 * ldc + col;
                float* p1 = p0 + (size_t)8 * ldc;
                p0[0] = acc[mi][nj][0] + b0;
                p0[1] = acc[mi][nj][1] + b1;
                p1[0] = acc[mi][nj][2] + b0;
                p1[1] = acc[mi][nj][3] + b1;
            }
        }
    }
}

// ===========================================================================
extern "C" void kernel_launch(void* const* d_in, const int* in_sizes, int n_in,
                              void* d_out, int out_size) {
    const float* x   = (const float*)d_in[0];
    const int*   sel = (const int*)d_in[1];
    const float* rw  = (const float*)d_in[2];
    const float* wt0 = (const float*)d_in[3];
    const float* bt0 = (const float*)d_in[4];
    const float* wp0 = (const float*)d_in[5];
    const float* bp0 = (const float*)d_in[6];
    const float* wt1 = (const float*)d_in[7];
    const float* bt1 = (const float*)d_in[8];
    const float* wp1 = (const float*)d_in[9];
    const float* bp1 = (const float*)d_in[10];
    const float* wt2 = (const float*)d_in[11];
    const float* bt2 = (const float*)d_in[12];
    const float* wp2 = (const float*)d_in[13];
    const float* bp2 = (const float*)d_in[14];
    float* out = (float*)d_out;

    float *px336, *pfeat;
    __nv_bfloat16 *pph, *ppl, *pfh, *pfl, *pwh, *pwl;
    cudaGetSymbolAddress((void**)&px336, g_x336);
    cudaGetSymbolAddress((void**)&pph, g_patch_h);
    cudaGetSymbolAddress((void**)&ppl, g_patch_l);
    cudaGetSymbolAddress((void**)&pfh, g_featA_h);
    cudaGetSymbolAddress((void**)&pfl, g_featA_l);
    cudaGetSymbolAddress((void**)&pfeat, g_feat);
    cudaGetSymbolAddress((void**)&pwh, g_wT_h);
    cudaGetSymbolAddress((void**)&pwl, g_wT_l);

    const int SMEM = 2 * STAGE_BYTES;   // 131072
    cudaFuncSetAttribute(gemm_mma<0>, cudaFuncAttributeMaxDynamicSharedMemorySize, SMEM);
    cudaFuncSetAttribute(gemm_mma<1>, cudaFuncAttributeMaxDynamicSharedMemorySize, SMEM);
    cudaFuncSetAttribute(gemm_mma<2>, cudaFuncAttributeMaxDynamicSharedMemorySize, SMEM);

    compute_weights_kernel<<<1, 192>>>(sel, rw);
    cudaMemsetAsync(d_out, 0, (size_t)out_size * sizeof(float), 0);

    // ---------------- Expert 0: g=32 c=1024, Ktower 588->640 ----------------
    {
        long long tot = 64LL * 1024 * 640;
        im2col_split_kernel<<<(unsigned)((tot + 255) / 256), 256>>>(x, pph, ppl, 32, 14, 448, 640, 0);
        transpose_split_kernel<<<dim3(1024 / 32, 640 / 32), dim3(32, 32)>>>(wt0, pwh, pwl, 588, 1024, 640);
        gemm_mma<0><<<dim3(8, 512), 256, SMEM>>>(640, 1024, 0,
            pph, ppl, pwh, pwl, bt0, nullptr, pfh, pfl, 1024);
        transpose_split_kernel<<<dim3(1024 / 32, 1024 / 32), dim3(32, 32)>>>(wp0, pwh, pwl, 1024, 1024, 1024);
        gemm_mma<2><<<dim3(8, 512), 256, SMEM>>>(1024, 1024, 0,
            pfh, pfl, pwh, pwl, bp0, out, nullptr, nullptr, 1024);
    }

    // ---------------- Expert 1: g=24 c=768, input resize ----------------
    {
        long long rtot = 64LL * 3 * 336 * 336;
        resize_input_kernel<<<(unsigned)((rtot + 255) / 256), 256>>>(x, px336);
        long long tot = 64LL * 576 * 640;
        im2col_split_kernel<<<(unsigned)((tot + 255) / 256), 256>>>(px336, pph, ppl, 24, 14, 336, 640, 1);
        transpose_split_kernel<<<dim3(768 / 32, 640 / 32), dim3(32, 32)>>>(wt1, pwh, pwl, 588, 768, 640);
        gemm_mma<1><<<dim3(6, 288), 256, SMEM>>>(640, 576, 1,
            pph, ppl, pwh, pwl, bt1, pfeat, nullptr, nullptr, 768);
        feat_resize_split_kernel<<<64 * 1024, 256>>>(pfeat, pfh, pfl, 24, 768, 1);
        transpose_split_kernel<<<dim3(1024 / 32, 768 / 32), dim3(32, 32)>>>(wp1, pwh, pwl, 768, 1024, 768);
        gemm_mma<2><<<dim3(8, 512), 256, SMEM>>>(768, 1024, 1,
            pfh, pfl, pwh, pwl, bp1, out, nullptr, nullptr, 1024);
    }

    // ---------------- Expert 2: g=14 c=1152, Ktower=3072 ----------------
    {
        long long tot = 64LL * 196 * 3072;
        im2col_split_kernel<<<(unsigned)((tot + 255) / 256), 256>>>(x, pph, ppl, 14, 32, 448, 3072, 2);
        transpose_split_kernel<<<dim3(1152 / 32, 3072 / 32), dim3(32, 32)>>>(wt2, pwh, pwl, 3072, 1152, 3072);
        gemm_mma<1><<<dim3(9, 98), 256, SMEM>>>(3072, 196, 2,
            pph, ppl, pwh, pwl, bt2, pfeat, nullptr, nullptr, 1152);
        feat_resize_split_kernel<<<64 * 1024, 256>>>(pfeat, pfh, pfl, 14, 1152, 2);
        transpose_split_kernel<<<dim3(1024 / 32, 1152 / 32), dim3(32, 32)>>>(wp2, pwh, pwl, 1152, 1024, 1152);
        gemm_mma<2><<<dim3(8, 512), 256, SMEM>>>(1152, 1024, 2,
            pfh, pfl, pwh, pwl, bp2, out, nullptr, nullptr, 1024);
    }
}

// round 8
// speedup vs baseline: 2.7353x; 1.2764x over previous
#include <cuda_runtime.h>
#include <cuda_bf16.h>
#include <cstdint>

// ===========================================================================
// VisionExperts via base-ISA tensor cores (mma.sync bf16, 3-pass split):
//   C = (Ah+Al)(Bh+Bl)^T ~= AhBh + AhBl + AlBh   (fp32 accumulate)
// cp.async 16B -> SW128 smem tiles (3-stage) -> ldmatrix -> HMMA.16816.
// 512 threads, 16 warps, warp tile 32x32, block tile 128x128, BK=64.
// ===========================================================================

// ---------------- device scratch (globals; no runtime alloc) ----------------
__device__ float         g_x336[21676032];        //  86.7 MB
__device__ __nv_bfloat16 g_patch_h[41943040];     //  84 MB   [M, Kpad]
__device__ __nv_bfloat16 g_patch_l[41943040];     //  84 MB
__device__ __nv_bfloat16 g_featA_h[75497472];     // 151 MB   [65536, c]
__device__ __nv_bfloat16 g_featA_l[75497472];     // 151 MB
__device__ float         g_feat[28311552];        // 113 MB   tower fp32 out (E1/E2)
__device__ __nv_bfloat16 g_wT_h[3538944];         //   7 MB   [N, Kpad]
__device__ __nv_bfloat16 g_wT_l[3538944];
__device__ float         g_w[192];                // routing weight [expert][b]

// ---------------- helpers ----------------
__device__ __forceinline__ uint32_t smem_u32(const void* p) {
    uint32_t a;
    asm("{ .reg .u64 t; cvta.to.shared.u64 t, %1; cvt.u32.u64 %0, t; }" : "=r"(a) : "l"(p));
    return a;
}
#define CP_ASYNC16(saddr, gptr) \
    asm volatile("cp.async.cg.shared.global [%0], [%1], 16;" :: "r"(saddr), "l"(gptr))
#define CP_COMMIT() asm volatile("cp.async.commit_group;" ::: "memory")
#define LDSM4(d0, d1, d2, d3, addr) \
    asm volatile("ldmatrix.sync.aligned.m8n8.x4.shared.b16 {%0,%1,%2,%3}, [%4];" \
                 : "=r"(d0), "=r"(d1), "=r"(d2), "=r"(d3) : "r"(addr))
#define MMA16816(d, a, b) \
    asm volatile("mma.sync.aligned.m16n8k16.row.col.f32.bf16.bf16.f32 " \
                 "{%0,%1,%2,%3}, {%4,%5,%6,%7}, {%8,%9}, {%0,%1,%2,%3};" \
                 : "+f"((d)[0]), "+f"((d)[1]), "+f"((d)[2]), "+f"((d)[3]) \
                 : "r"((a)[0]), "r"((a)[1]), "r"((a)[2]), "r"((a)[3]), \
                   "r"((b)[0]), "r"((b)[1]))

#define SW128(o) ((o) ^ (((o) >> 3) & 0x70))

__device__ __forceinline__ void split2(float v, __nv_bfloat16& h, __nv_bfloat16& l) {
    h = __float2bfloat16(v);
    l = __float2bfloat16(v - __bfloat162float(h));
}

// ---------------- small kernels ----------------
__global__ void compute_weights_kernel(const int* __restrict__ sel,
                                       const float* __restrict__ rw) {
    int i = threadIdx.x;
    if (i < 192) {
        int e = i / 64, b = i % 64;
        float w = 0.0f;
        if (sel[2 * b + 0] == e) w += rw[2 * b + 0];
        if (sel[2 * b + 1] == e) w += rw[2 * b + 1];
        g_w[i] = w;
    }
}

__global__ void resize_input_kernel(const float* __restrict__ x, float* __restrict__ y) {
    long long idx = (long long)blockIdx.x * blockDim.x + threadIdx.x;
    const long long total = 64LL * 3 * 336 * 336;
    if (idx >= total) return;
    int ox = (int)(idx % 336);
    int oy = (int)((idx / 336) % 336);
    int bc = (int)(idx / (336 * 336));
    int b = bc / 3;
    if (g_w[64 + b] == 0.0f) return;
    const float scale = 447.0f / 335.0f;
    float fy = oy * scale, fx = ox * scale;
    int y0 = (int)floorf(fy); int y1 = min(y0 + 1, 447);
    int x0 = (int)floorf(fx); int x1 = min(x0 + 1, 447);
    float ty = fy - y0, tx = fx - x0;
    const float* p = x + (size_t)bc * 448 * 448;
    float v00 = p[y0 * 448 + x0], v01 = p[y0 * 448 + x1];
    float v10 = p[y1 * 448 + x0], v11 = p[y1 * 448 + x1];
    float r0 = v00 + (v01 - v00) * tx;
    float r1 = v10 + (v11 - v10) * tx;
    y[idx] = r0 + (r1 - r0) * ty;
}

// im2col + bf16 split, K padded to Kpad with zeros
__global__ void im2col_split_kernel(const float* __restrict__ src,
                                    __nv_bfloat16* __restrict__ dh,
                                    __nv_bfloat16* __restrict__ dl,
                                    int g, int p, int s, int Kpad, int expert) {
    long long idx = (long long)blockIdx.x * blockDim.x + threadIdx.x;
    long long total = 64LL * g * g * Kpad;
    if (idx >= total) return;
    int k = (int)(idx % Kpad);
    long long t = idx / Kpad;
    int token = (int)(t % (g * g));
    int b = (int)(t / (g * g));
    if (g_w[expert * 64 + b] == 0.0f) return;
    float v = 0.0f;
    int K = 3 * p * p;
    if (k < K) {
        int ch = k / (p * p);
        int r = k % (p * p);
        int py = r / p, px = r % p;
        int gy = token / g, gx = token % g;
        v = src[(((size_t)b * 3 + ch) * s + (gy * p + py)) * s + (gx * p + px)];
    }
    __nv_bfloat16 h, l; split2(v, h, l);
    dh[idx] = h; dl[idx] = l;
}

// w[K,N] -> wT[N,Kpad] (zero pad) + bf16 split, 32x32 smem tiles
__global__ void transpose_split_kernel(const float* __restrict__ w,
                                       __nv_bfloat16* __restrict__ th,
                                       __nv_bfloat16* __restrict__ tl,
                                       int K, int N, int Kpad) {
    __shared__ float t[32][33];
    int k0 = blockIdx.y * 32, n0 = blockIdx.x * 32;
    int kk = k0 + threadIdx.y, nn = n0 + threadIdx.x;
    t[threadIdx.y][threadIdx.x] = (kk < K && nn < N) ? w[(size_t)kk * N + nn] : 0.0f;
    __syncthreads();
    int on = n0 + threadIdx.y, ok = k0 + threadIdx.x;
    if (on < N && ok < Kpad) {
        __nv_bfloat16 h, l; split2(t[threadIdx.x][threadIdx.y], h, l);
        th[(size_t)on * Kpad + ok] = h;
        tl[(size_t)on * Kpad + ok] = l;
    }
}

// feature grid resize g x g -> 32 x 32 with bf16 split output
__global__ void feat_resize_split_kernel(const float* __restrict__ in,
                                         __nv_bfloat16* __restrict__ oh,
                                         __nv_bfloat16* __restrict__ ol,
                                         int g, int c, int expert) {
    int token = blockIdx.x & 1023;
    int b = blockIdx.x >> 10;
    if (g_w[expert * 64 + b] == 0.0f) return;
    int oy = token >> 5, ox = token & 31;
    float scale = (float)(g - 1) / 31.0f;
    float fy = oy * scale, fx = ox * scale;
    int y0 = (int)floorf(fy), x0 = (int)floorf(fx);
    int y1 = min(y0 + 1, g - 1), x1 = min(x0 + 1, g - 1);
    float ty = fy - y0, tx = fx - x0;
    float w00 = (1.f - ty) * (1.f - tx), w01 = (1.f - ty) * tx;
    float w10 = ty * (1.f - tx),         w11 = ty * tx;
    const float* base = in + (size_t)b * g * g * c;
    const float* p00 = base + (size_t)(y0 * g + x0) * c;
    const float* p01 = base + (size_t)(y0 * g + x1) * c;
    const float* p10 = base + (size_t)(y1 * g + x0) * c;
    const float* p11 = base + (size_t)(y1 * g + x1) * c;
    size_t row = (size_t)b * 1024 + token;
    for (int i = threadIdx.x; i < c; i += blockDim.x) {
        float v = w00 * p00[i] + w01 * p01[i] + w10 * p10[i] + w11 * p11[i];
        __nv_bfloat16 h, l; split2(v, h, l);
        oh[row * c + i] = h; ol[row * c + i] = l;
    }
}

// ===========================================================================
// mma.sync GEMM: D[128x128] = (Ah+Al)[128,K] @ (Bh+Bl)[128,K]^T (3 passes).
// SW128 smem stages of BK=64 (Ah|Al|Bh|Bl @ 16KB each), 3-stage pipeline.
// 512 threads, 16 warps, warp tile 32x32 (warp grid 4x4).
// MODE 0: tower -> split bf16 (Ch/Cl, ldc)    MODE 1: tower -> fp32 (C, ldc)
// MODE 2: proj  -> C[row*1024+col] += w_b * (v + bias)
// ===========================================================================
#define STAGE_BYTES 65536
#define NSTAGE 3

__device__ __forceinline__ void load_stage(
    uint32_t sb, const __nv_bfloat16* Ah, const __nv_bfloat16* Al,
    const __nv_bfloat16* Bh, const __nv_bfloat16* Bl,
    int rowStart, int colStart, int Kpad, int k0, int tid) {
#pragma unroll 8
    for (int c = tid; c < 4096; c += 512) {
        int half = (c >> 10) & 1;
        int cc = c & 1023;
        int r = cc >> 3, kc = cc & 7;
        const __nv_bfloat16* gp;
        uint32_t so;
        if (c < 2048) {
            gp = (half ? Al : Ah) + (size_t)(rowStart + r) * Kpad + k0 + kc * 8;
            so = sb + half * 16384 + SW128(r * 128 + kc * 16);
        } else {
            gp = (half ? Bl : Bh) + (size_t)(colStart + r) * Kpad + k0 + kc * 8;
            so = sb + 32768 + half * 16384 + SW128(r * 128 + kc * 16);
        }
        CP_ASYNC16(so, (const void*)gp);
    }
}

template <int MODE>
__global__ __launch_bounds__(512, 1) void gemm_mma(
    int Kpad, int tps, int expert,
    const __nv_bfloat16* __restrict__ Ah, const __nv_bfloat16* __restrict__ Al,
    const __nv_bfloat16* __restrict__ Bh, const __nv_bfloat16* __restrict__ Bl,
    const float* __restrict__ bias,
    float* __restrict__ C, __nv_bfloat16* __restrict__ Ch, __nv_bfloat16* __restrict__ Cl,
    int ldc) {
    const int tid = threadIdx.x;
    const int wid = tid >> 5, lane = tid & 31;
    const int rowStart = blockIdx.y * 128;
    const int colStart = blockIdx.x * 128;

    // routing skip: all samples covered by this M-block unrouted -> no work
    {
        int bLo = rowStart / tps, bHi = (rowStart + 127) / tps;
        bool any = false;
        for (int b = bLo; b <= bHi; ++b) any = any || (g_w[expert * 64 + b] != 0.0f);
        if (!any) return;
    }

    extern __shared__ __align__(1024) char smem[];
    const uint32_t sb0 = smem_u32(smem);

    const int wm = (wid >> 2) * 32;      // warp m-offset within block (4 groups)
    const int wn = (wid & 3) * 32;       // warp n-offset within block (4 groups)

    float acc[2][4][4];
#pragma unroll
    for (int i = 0; i < 2; ++i)
#pragma unroll
        for (int j = 0; j < 4; ++j)
#pragma unroll
            for (int r = 0; r < 4; ++r) acc[i][j][r] = 0.0f;

    const int KBn = Kpad >> 6;

    // lane-dependent ldmatrix address components
    const int arow = wm + (lane & 15);
    const int alo  = lane >> 4;                         // 0/1: k-chunk half
    const int bmat = lane >> 3;
    const int brow = ((bmat >> 1) << 3) + (lane & 7);   // n-row within 16
    const int bko  = bmat & 1;                          // k-chunk half

    // prologue: stages 0 and 1 in flight
    load_stage(sb0, Ah, Al, Bh, Bl, rowStart, colStart, Kpad, 0, tid);
    CP_COMMIT();
    if (KBn > 1) {
        load_stage(sb0 + STAGE_BYTES, Ah, Al, Bh, Bl, rowStart, colStart, Kpad, 64, tid);
        CP_COMMIT();
    }

    int stage = 0;
    for (int kb = 0; kb < KBn; ++kb) {
        if (kb + 1 < KBn)
            asm volatile("cp.async.wait_group 1;" ::: "memory");
        else
            asm volatile("cp.async.wait_group 0;" ::: "memory");
        __syncthreads();

        const uint32_t sb = sb0 + stage * STAGE_BYTES;
#pragma unroll
        for (int kk = 0; kk < 4; ++kk) {
            uint32_t ah[2][4], al[2][4], bh[4][2], bl[4][2];
#pragma unroll
            for (int mi = 0; mi < 2; ++mi) {
                uint32_t off = SW128((arow + 16 * mi) * 128 + (kk * 2 + alo) * 16);
                LDSM4(ah[mi][0], ah[mi][1], ah[mi][2], ah[mi][3], sb + off);
                LDSM4(al[mi][0], al[mi][1], al[mi][2], al[mi][3], sb + 16384 + off);
            }
#pragma unroll
            for (int p = 0; p < 2; ++p) {
                uint32_t off = SW128((wn + p * 16 + brow) * 128 + (kk * 2 + bko) * 16);
                LDSM4(bh[2 * p][0], bh[2 * p][1], bh[2 * p + 1][0], bh[2 * p + 1][1],
                      sb + 32768 + off);
                LDSM4(bl[2 * p][0], bl[2 * p][1], bl[2 * p + 1][0], bl[2 * p + 1][1],
                      sb + 49152 + off);
            }
#pragma unroll
            for (int mi = 0; mi < 2; ++mi)
#pragma unroll
                for (int nj = 0; nj < 4; ++nj) {
                    MMA16816(acc[mi][nj], ah[mi], bh[nj]);
                    MMA16816(acc[mi][nj], ah[mi], bl[nj]);
                    MMA16816(acc[mi][nj], al[mi], bh[nj]);
                }
        }

        if (kb + 2 < KBn) {
            int ns = stage + 2; if (ns >= NSTAGE) ns -= NSTAGE;
            load_stage(sb0 + ns * STAGE_BYTES, Ah, Al, Bh, Bl,
                       rowStart, colStart, Kpad, (kb + 2) << 6, tid);
            CP_COMMIT();
        }
        if (++stage == NSTAGE) stage = 0;
    }

    // -------- epilogue straight from registers --------
    const int tq = lane >> 2;            // row within 8
    const int tr2 = (lane & 3) * 2;      // col pair
    if (MODE == 2) {
        float w = g_w[expert * 64 + (rowStart >> 10)];
#pragma unroll
        for (int nj = 0; nj < 4; ++nj) {
            int col = colStart + wn + nj * 8 + tr2;
            float b0 = bias[col], b1 = bias[col + 1];
#pragma unroll
            for (int mi = 0; mi < 2; ++mi) {
                int row0 = rowStart + wm + mi * 16 + tq;
                float* p0 = C + (size_t)row0 * 1024 + col;
                float* p1 = p0 + 8 * 1024;
                p0[0] += w * (acc[mi][nj][0] + b0);
                p0[1] += w * (acc[mi][nj][1] + b1);
                p1[0] += w * (acc[mi][nj][2] + b0);
                p1[1] += w * (acc[mi][nj][3] + b1);
            }
        }
    } else if (MODE == 0) {
#pragma unroll
        for (int nj = 0; nj < 4; ++nj) {
            int col = colStart + wn + nj * 8 + tr2;
            float b0 = bias[col], b1 = bias[col + 1];
#pragma unroll
            for (int mi = 0; mi < 2; ++mi) {
                int row0 = rowStart + wm + mi * 16 + tq;
#pragma unroll
                for (int h = 0; h < 2; ++h) {
                    int row = row0 + h * 8;
                    float v0 = acc[mi][nj][2 * h + 0] + b0;
                    float v1 = acc[mi][nj][2 * h + 1] + b1;
                    __nv_bfloat16 h0, l0, h1, l1;
                    split2(v0, h0, l0); split2(v1, h1, l1);
                    __nv_bfloat162 ph; ph.x = h0; ph.y = h1;
                    __nv_bfloat162 pl; pl.x = l0; pl.y = l1;
                    *(__nv_bfloat162*)(Ch + (size_t)row * ldc + col) = ph;
                    *(__nv_bfloat162*)(Cl + (size_t)row * ldc + col) = pl;
                }
            }
        }
    } else {
#pragma unroll
        for (int nj = 0; nj < 4; ++nj) {
            int col = colStart + wn + nj * 8 + tr2;
            float b0 = bias[col], b1 = bias[col + 1];
#pragma unroll
            for (int mi = 0; mi < 2; ++mi) {
                int row0 = rowStart + wm + mi * 16 + tq;
                float* p0 = C + (size_t)row0 * ldc + col;
                float* p1 = p0 + (size_t)8 * ldc;
                p0[0] = acc[mi][nj][0] + b0;
                p0[1] = acc[mi][nj][1] + b1;
                p1[0] = acc[mi][nj][2] + b0;
                p1[1] = acc[mi][nj][3] + b1;
            }
        }
    }
}

// ===========================================================================
extern "C" void kernel_launch(void* const* d_in, const int* in_sizes, int n_in,
                              void* d_out, int out_size) {
    const float* x   = (const float*)d_in[0];
    const int*   sel = (const int*)d_in[1];
    const float* rw  = (const float*)d_in[2];
    const float* wt0 = (const float*)d_in[3];
    const float* bt0 = (const float*)d_in[4];
    const float* wp0 = (const float*)d_in[5];
    const float* bp0 = (const float*)d_in[6];
    const float* wt1 = (const float*)d_in[7];
    const float* bt1 = (const float*)d_in[8];
    const float* wp1 = (const float*)d_in[9];
    const float* bp1 = (const float*)d_in[10];
    const float* wt2 = (const float*)d_in[11];
    const float* bt2 = (const float*)d_in[12];
    const float* wp2 = (const float*)d_in[13];
    const float* bp2 = (const float*)d_in[14];
    float* out = (float*)d_out;

    float *px336, *pfeat;
    __nv_bfloat16 *pph, *ppl, *pfh, *pfl, *pwh, *pwl;
    cudaGetSymbolAddress((void**)&px336, g_x336);
    cudaGetSymbolAddress((void**)&pph, g_patch_h);
    cudaGetSymbolAddress((void**)&ppl, g_patch_l);
    cudaGetSymbolAddress((void**)&pfh, g_featA_h);
    cudaGetSymbolAddress((void**)&pfl, g_featA_l);
    cudaGetSymbolAddress((void**)&pfeat, g_feat);
    cudaGetSymbolAddress((void**)&pwh, g_wT_h);
    cudaGetSymbolAddress((void**)&pwl, g_wT_l);

    const int SMEM = NSTAGE * STAGE_BYTES;   // 196608
    cudaFuncSetAttribute(gemm_mma<0>, cudaFuncAttributeMaxDynamicSharedMemorySize, SMEM);
    cudaFuncSetAttribute(gemm_mma<1>, cudaFuncAttributeMaxDynamicSharedMemorySize, SMEM);
    cudaFuncSetAttribute(gemm_mma<2>, cudaFuncAttributeMaxDynamicSharedMemorySize, SMEM);

    compute_weights_kernel<<<1, 192>>>(sel, rw);
    cudaMemsetAsync(d_out, 0, (size_t)out_size * sizeof(float), 0);

    // ---------------- Expert 0: g=32 c=1024, Ktower 588->640 ----------------
    {
        long long tot = 64LL * 1024 * 640;
        im2col_split_kernel<<<(unsigned)((tot + 255) / 256), 256>>>(x, pph, ppl, 32, 14, 448, 640, 0);
        transpose_split_kernel<<<dim3(1024 / 32, 640 / 32), dim3(32, 32)>>>(wt0, pwh, pwl, 588, 1024, 640);
        gemm_mma<0><<<dim3(8, 512), 512, SMEM>>>(640, 1024, 0,
            pph, ppl, pwh, pwl, bt0, nullptr, pfh, pfl, 1024);
        transpose_split_kernel<<<dim3(1024 / 32, 1024 / 32), dim3(32, 32)>>>(wp0, pwh, pwl, 1024, 1024, 1024);
        gemm_mma<2><<<dim3(8, 512), 512, SMEM>>>(1024, 1024, 0,
            pfh, pfl, pwh, pwl, bp0, out, nullptr, nullptr, 1024);
    }

    // ---------------- Expert 1: g=24 c=768, input resize ----------------
    {
        long long rtot = 64LL * 3 * 336 * 336;
        resize_input_kernel<<<(unsigned)((rtot + 255) / 256), 256>>>(x, px336);
        long long tot = 64LL * 576 * 640;
        im2col_split_kernel<<<(unsigned)((tot + 255) / 256), 256>>>(px336, pph, ppl, 24, 14, 336, 640, 1);
        transpose_split_kernel<<<dim3(768 / 32, 640 / 32), dim3(32, 32)>>>(wt1, pwh, pwl, 588, 768, 640);
        gemm_mma<1><<<dim3(6, 288), 512, SMEM>>>(640, 576, 1,
            pph, ppl, pwh, pwl, bt1, pfeat, nullptr, nullptr, 768);
        feat_resize_split_kernel<<<64 * 1024, 256>>>(pfeat, pfh, pfl, 24, 768, 1);
        transpose_split_kernel<<<dim3(1024 / 32, 768 / 32), dim3(32, 32)>>>(wp1, pwh, pwl, 768, 1024, 768);
        gemm_mma<2><<<dim3(8, 512), 512, SMEM>>>(768, 1024, 1,
            pfh, pfl, pwh, pwl, bp1, out, nullptr, nullptr, 1024);
    }

    // ---------------- Expert 2: g=14 c=1152, Ktower=3072 ----------------
    {
        long long tot = 64LL * 196 * 3072;
        im2col_split_kernel<<<(unsigned)((tot + 255) / 256), 256>>>(x, pph, ppl, 14, 32, 448, 3072, 2);
        transpose_split_kernel<<<dim3(1152 / 32, 3072 / 32), dim3(32, 32)>>>(wt2, pwh, pwl, 3072, 1152, 3072);
        gemm_mma<1><<<dim3(9, 98), 512, SMEM>>>(3072, 196, 2,
            pph, ppl, pwh, pwl, bt2, pfeat, nullptr, nullptr, 1152);
        feat_resize_split_kernel<<<64 * 1024, 256>>>(pfeat, pfh, pfl, 14, 1152, 2);
        transpose_split_kernel<<<dim3(1024 / 32, 1152 / 32), dim3(32, 32)>>>(wp2, pwh, pwl, 1152, 1024, 1152);
        gemm_mma<2><<<dim3(8, 512), 512, SMEM>>>(1152, 1024, 2,
            pfh, pfl, pwh, pwl, bp2, out, nullptr, nullptr, 1024);
    }
}